// round 4
// baseline (speedup 1.0000x reference)
#include <cuda_runtime.h>
#include <cstdint>

#define BB 64
#define TT 512
#define HH 512
#define EE 256
#define G4 2048          // 4*H
#define NCTA 128         // persistent CTAs in scan (<= 148 SMs, all co-resident)

// ---------------- device scratch (static: no allocations allowed) ----------------
__device__ float    g_gates[(size_t)TT * BB * G4];  // 256 MB: gates_x, layout [t][b][j][gate]
__device__ float    g_h[2][BB * HH];                // double-buffered carry h (post-reset)
__device__ int      g_rT[TT * BB];                  // reset transposed [t][b]
__device__ unsigned g_bar[TT];                      // per-step barrier counters

// ---------------- init: zero state/barriers, build rT + mask output --------------
__global__ void init_kernel(const int* __restrict__ lengths,
                            const int* __restrict__ resets,
                            float* __restrict__ out_mask) {
    int idx = blockIdx.x * blockDim.x + threadIdx.x;   // 0..32767
    if (idx < TT) g_bar[idx] = 0u;
    if (idx < BB * HH) { g_h[0][idx] = 0.f; g_h[1][idx] = 0.f; }
    int b = idx >> 9;
    int t = idx & 511;
    int rv = resets[b * TT + t];
    g_rT[t * BB + b] = rv;
    out_mask[b * TT + t] = (t < lengths[b]) ? 1.f : 0.f;
}

// ---------------- gates_x GEMM with fused embedding gather -----------------------
// C[m][n], m = t*64 + b (block y = t), n = j*4 + g  -> W_ih row wr = g*512 + j
// g_gates[m*2048 + n] = sum_e emb[tok(b,t)][e] * W_ih[wr][e] + b_ih[wr] + b_hh[wr]
__global__ __launch_bounds__(256) void gates_kernel(const int* __restrict__ inputs,
                                                    const float* __restrict__ emb,
                                                    const float* __restrict__ Wih,
                                                    const float* __restrict__ bih,
                                                    const float* __restrict__ bhh) {
    __shared__ float As[64 * 69];   // [b][k] pitch 69
    __shared__ float Bs[64 * 69];   // [n][k] pitch 69
    __shared__ int   tok[64];
    __shared__ float bias_s[64];

    const int t   = blockIdx.y;     // 0..511
    const int nb  = blockIdx.x;     // 0..31 (64 cols each)
    const int tid = threadIdx.x;
    const int tx  = tid & 15;
    const int ty  = tid >> 4;

    if (tid < 64) {
        tok[tid] = inputs[tid * TT + t];
    } else if (tid < 128) {
        int n  = nb * 64 + (tid - 64);
        int wr = (n & 3) * 512 + (n >> 2);
        bias_s[tid - 64] = bih[wr] + bhh[wr];
    }
    __syncthreads();

    float acc[4][4] = {};
    for (int kc = 0; kc < EE; kc += 64) {
#pragma unroll
        for (int i = 0; i < 16; i++) {
            int idx = i * 256 + tid;
            int mi  = idx >> 6;      // row within tile (= batch b)
            int kk  = idx & 63;
            As[mi * 69 + kk] = emb[(size_t)tok[mi] * EE + kc + kk];
            int n  = nb * 64 + mi;
            int wr = (n & 3) * 512 + (n >> 2);
            Bs[mi * 69 + kk] = Wih[wr * EE + kc + kk];
        }
        __syncthreads();
#pragma unroll 8
        for (int kk = 0; kk < 64; kk++) {
            float a0 = As[(ty * 4 + 0) * 69 + kk];
            float a1 = As[(ty * 4 + 1) * 69 + kk];
            float a2 = As[(ty * 4 + 2) * 69 + kk];
            float a3 = As[(ty * 4 + 3) * 69 + kk];
            float b0 = Bs[(tx * 4 + 0) * 69 + kk];
            float b1 = Bs[(tx * 4 + 1) * 69 + kk];
            float b2 = Bs[(tx * 4 + 2) * 69 + kk];
            float b3 = Bs[(tx * 4 + 3) * 69 + kk];
            acc[0][0] = fmaf(a0, b0, acc[0][0]);
            acc[0][1] = fmaf(a0, b1, acc[0][1]);
            acc[0][2] = fmaf(a0, b2, acc[0][2]);
            acc[0][3] = fmaf(a0, b3, acc[0][3]);
            acc[1][0] = fmaf(a1, b0, acc[1][0]);
            acc[1][1] = fmaf(a1, b1, acc[1][1]);
            acc[1][2] = fmaf(a1, b2, acc[1][2]);
            acc[1][3] = fmaf(a1, b3, acc[1][3]);
            acc[2][0] = fmaf(a2, b0, acc[2][0]);
            acc[2][1] = fmaf(a2, b1, acc[2][1]);
            acc[2][2] = fmaf(a2, b2, acc[2][2]);
            acc[2][3] = fmaf(a2, b3, acc[2][3]);
            acc[3][0] = fmaf(a3, b0, acc[3][0]);
            acc[3][1] = fmaf(a3, b1, acc[3][1]);
            acc[3][2] = fmaf(a3, b2, acc[3][2]);
            acc[3][3] = fmaf(a3, b3, acc[3][3]);
        }
        __syncthreads();
    }

    float* gp = g_gates + (size_t)(t * 64) * G4 + nb * 64;
#pragma unroll
    for (int r = 0; r < 4; r++) {
        float4 v;
        v.x = acc[r][0] + bias_s[tx * 4 + 0];
        v.y = acc[r][1] + bias_s[tx * 4 + 1];
        v.z = acc[r][2] + bias_s[tx * 4 + 2];
        v.w = acc[r][3] + bias_s[tx * 4 + 3];
        *reinterpret_cast<float4*>(gp + (size_t)(ty * 4 + r) * G4 + tx * 4) = v;
    }
}

// ---------------- persistent LSTM scan -------------------------------------------
// CTA cta owns hidden units j in [cta*4, cta*4+4). Thread: b = tid>>2, jl = tid&3.
// W_hh slice (16 rows x 512) lives in SMEM for all 512 steps. c-state in registers.
// h carry is DOUBLE-BUFFERED in gmem: step t reads buf[t&1], writes buf[(t+1)&1].
// h SMEM layout: slot(k,b) = k*64 + ((b + (k>>2)) & 63)  -- per-row ROTATION of b:
// injective (permutation within each k-row), conflict-free for both the staging
// writes (bank = (b2+q) mod 32, distinct per lane) and the GEMV reads (rotated-
// consecutive b). [The R1/R2 additive shift collided at k=127/128 etc. -> 2e-2 err]
__global__ __launch_bounds__(256, 1) void scan_kernel(const float* __restrict__ Whh,
                                                      const int* __restrict__ lengths,
                                                      float* __restrict__ d_out) {
    extern __shared__ float sm[];
    float* Ws = sm;               // [k][16] : 512*16 floats = 32 KB
    float* hs = sm + 512 * 16;    // rotated h: 512*64 floats = 128 KB

    const int tid = threadIdx.x;
    const int b   = tid >> 2;     // 0..63
    const int jl  = tid & 3;      // 0..3
    const int j   = blockIdx.x * 4 + jl;

    // stage W slice: Ws[k*16 + r], r = jl_*4 + g  ->  Whh[(g*512 + j0+jl_)*512 + k]
    for (int idx = tid; idx < 16 * 512; idx += 256) {
        int k = idx & 511;
        int r = idx >> 9;   // 0..15
        int g = r & 3;
        int jj = blockIdx.x * 4 + (r >> 2);
        Ws[k * 16 + r] = Whh[((size_t)(g * 512 + jj)) * 512 + k];
    }

    float c_reg = 0.f;
    const int len_b = lengths[b];

    const float4* gx4 = reinterpret_cast<const float4*>(g_gates);
    const float4* Ws4 = reinterpret_cast<const float4*>(Ws);
    float* hT = d_out + (size_t)BB * TT * HH;
    float* cT = hT + BB * HH;

    __syncthreads();

    for (int t = 0; t < TT; t++) {
        const float4* gh4 = reinterpret_cast<const float4*>(g_h[t & 1]);
        float*        ghw = g_h[(t + 1) & 1];

        // ---- stage h (bypass L1: other SMs rewrote it last step) ----
#pragma unroll 8
        for (int i = 0; i < 32; i++) {
            int idx4 = i * 256 + tid;         // 0..8191 float4s
            int b2   = idx4 >> 7;             // batch row
            int q    = idx4 & 127;            // k0 = q*4
            float4 v = __ldcg(&gh4[idx4]);
            int base = (q * 4) * 64 + ((b2 + q) & 63);   // slot(k,b)=k*64+((b+(k>>2))&63)
            hs[base      ] = v.x;
            hs[base + 64 ] = v.y;
            hs[base + 128] = v.z;
            hs[base + 192] = v.w;
        }
        __syncthreads();

        // ---- gates for (b, j): acc = gx + h . W_hh^T ----
        float4 acc = __ldg(&gx4[(size_t)(t * BB + b) * 512 + j]);
#pragma unroll 8
        for (int k = 0; k < HH; k++) {
            float4 w = Ws4[k * 4 + jl];                       // 4 gates of jl
            float hv = hs[k * 64 + ((b + (k >> 2)) & 63)];
            acc.x = fmaf(hv, w.x, acc.x);
            acc.y = fmaf(hv, w.y, acc.y);
            acc.z = fmaf(hv, w.z, acc.z);
            acc.w = fmaf(hv, w.w, acc.w);
        }

        // ---- activations + state update ----
        float ig = 1.f / (1.f + expf(-acc.x));
        float fg = 1.f / (1.f + expf(-acc.y));
        float gg = tanhf(acc.z);
        float og = 1.f / (1.f + expf(-acc.w));
        float c_new = fg * c_reg + ig * gg;
        float h_new = og * tanhf(c_new);

        float h_prev = hs[j * 64 + ((b + (j >> 2)) & 63)];
        float m  = (t < len_b) ? 1.f : 0.f;
        float h_nx = m * h_new + (1.f - m) * h_prev;
        float c_nx = m * c_new + (1.f - m) * c_reg;

        d_out[((size_t)b * TT + t) * HH + j] = h_nx;

        float rr = (float)g_rT[t * BB + b];
        c_reg = c_nx * (1.f - rr);
        float h_carry = h_nx * (1.f - rr);
        ghw[b * HH + j] = h_carry;

        if (t == TT - 1) {
            hT[b * HH + j] = h_carry;
            cT[b * HH + j] = c_reg;
        }

        // ---- grid barrier: orders this step's carry writes before next step's reads
        __threadfence();
        __syncthreads();      // also protects hs against next step's restage
        if (t < TT - 1) {
            if (tid == 0) {
                unsigned arrived = atomicAdd(&g_bar[t], 1u) + 1u;
                if (arrived < (unsigned)NCTA) {
                    while (*((volatile unsigned*)&g_bar[t]) < (unsigned)NCTA) {
                        __nanosleep(64);
                    }
                }
            }
            __syncthreads();
        }
    }
}

// ---------------- launch ---------------------------------------------------------
extern "C" void kernel_launch(void* const* d_in, const int* in_sizes, int n_in,
                              void* d_out, int out_size) {
    const int*   inputs  = (const int*)d_in[0];
    const int*   lengths = (const int*)d_in[1];
    const int*   resets  = (const int*)d_in[2];
    const float* emb     = (const float*)d_in[3];
    const float* Wih     = (const float*)d_in[4];
    const float* Whh     = (const float*)d_in[5];
    const float* bih     = (const float*)d_in[6];
    const float* bhh     = (const float*)d_in[7];
    float* out = (float*)d_out;
    float* out_mask = out + (size_t)BB * TT * HH + 2 * (size_t)BB * HH;

    const int SMEM_SCAN = (512 * 16 + 512 * 64) * (int)sizeof(float);  // 163840 B
    cudaFuncSetAttribute(scan_kernel, cudaFuncAttributeMaxDynamicSharedMemorySize, SMEM_SCAN);

    init_kernel<<<128, 256>>>(lengths, resets, out_mask);
    gates_kernel<<<dim3(32, 512), 256>>>(inputs, emb, Wih, bih, bhh);
    scan_kernel<<<NCTA, 256, SMEM_SCAN>>>(Whh, lengths, out);
}

// round 5
// speedup vs baseline: 1.0642x; 1.0642x over previous
#include <cuda_runtime.h>
#include <cstdint>

#define BB 64
#define TT 512
#define HH 512
#define EE 256
#define G4 2048          // 4*H
#define NCTA 128         // persistent CTAs in scan (<= 148 SMs, all co-resident)
#define PH  516          // hs row pitch in floats: 2064B = 16B-aligned, 516 mod 32 = 4

// ---------------- device scratch (static: no allocations allowed) ----------------
__device__ float    g_gates[(size_t)TT * BB * G4];  // 256 MB: gates_x, layout [t][b][j][gate]
__device__ float    g_h[2][BB * HH];                // double-buffered carry h (post-reset)
__device__ int      g_rT[TT * BB];                  // reset transposed [t][b]
__device__ unsigned g_bar[TT];                      // per-step barrier counters

// ---------------- small asm helpers ----------------------------------------------
__device__ __forceinline__ unsigned long long pk2(float lo, float hi) {
    unsigned long long r;
    asm("mov.b64 %0, {%1,%2};" : "=l"(r) : "f"(lo), "f"(hi));
    return r;
}
__device__ __forceinline__ float2 upk2(unsigned long long v) {
    float2 r;
    asm("mov.b64 {%0,%1}, %2;" : "=f"(r.x), "=f"(r.y) : "l"(v));
    return r;
}
#define FFMA2(acc, a, b) \
    asm("fma.rn.f32x2 %0, %1, %2, %0;" : "+l"(acc) : "l"(a), "l"(b))

__device__ __forceinline__ unsigned smem_u32(const void* p) {
    return (unsigned)__cvta_generic_to_shared(p);
}
__device__ __forceinline__ unsigned long long lds_b64(unsigned addr) {
    unsigned long long r;
    asm("ld.shared.b64 %0, [%1];" : "=l"(r) : "r"(addr));
    return r;
}
__device__ __forceinline__ void lds_v2u64(unsigned addr, unsigned long long& a,
                                          unsigned long long& b) {
    asm("ld.shared.v2.u64 {%0,%1}, [%2];" : "=l"(a), "=l"(b) : "r"(addr));
}
__device__ __forceinline__ void sts_v4f32(unsigned addr, float4 v) {
    asm volatile("st.shared.v4.f32 [%0], {%1,%2,%3,%4};"
                 :: "r"(addr), "f"(v.x), "f"(v.y), "f"(v.z), "f"(v.w));
}

// ---------------- init: zero state/barriers, build rT + mask output --------------
__global__ void init_kernel(const int* __restrict__ lengths,
                            const int* __restrict__ resets,
                            float* __restrict__ out_mask) {
    int idx = blockIdx.x * blockDim.x + threadIdx.x;   // 0..32767
    if (idx < TT) g_bar[idx] = 0u;
    if (idx < BB * HH) { g_h[0][idx] = 0.f; g_h[1][idx] = 0.f; }
    int b = idx >> 9;
    int t = idx & 511;
    int rv = resets[b * TT + t];
    g_rT[t * BB + b] = rv;
    out_mask[b * TT + t] = (t < lengths[b]) ? 1.f : 0.f;
}

// ---------------- gates_x GEMM with fused embedding gather (unchanged, proven) ---
__global__ __launch_bounds__(256) void gates_kernel(const int* __restrict__ inputs,
                                                    const float* __restrict__ emb,
                                                    const float* __restrict__ Wih,
                                                    const float* __restrict__ bih,
                                                    const float* __restrict__ bhh) {
    __shared__ float As[64 * 69];   // [b][k] pitch 69
    __shared__ float Bs[64 * 69];   // [n][k] pitch 69
    __shared__ int   tok[64];
    __shared__ float bias_s[64];

    const int t   = blockIdx.y;
    const int nb  = blockIdx.x;
    const int tid = threadIdx.x;
    const int tx  = tid & 15;
    const int ty  = tid >> 4;

    if (tid < 64) {
        tok[tid] = inputs[tid * TT + t];
    } else if (tid < 128) {
        int n  = nb * 64 + (tid - 64);
        int wr = (n & 3) * 512 + (n >> 2);
        bias_s[tid - 64] = bih[wr] + bhh[wr];
    }
    __syncthreads();

    float acc[4][4] = {};
    for (int kc = 0; kc < EE; kc += 64) {
#pragma unroll
        for (int i = 0; i < 16; i++) {
            int idx = i * 256 + tid;
            int mi  = idx >> 6;
            int kk  = idx & 63;
            As[mi * 69 + kk] = emb[(size_t)tok[mi] * EE + kc + kk];
            int n  = nb * 64 + mi;
            int wr = (n & 3) * 512 + (n >> 2);
            Bs[mi * 69 + kk] = Wih[wr * EE + kc + kk];
        }
        __syncthreads();
#pragma unroll 8
        for (int kk = 0; kk < 64; kk++) {
            float a0 = As[(ty * 4 + 0) * 69 + kk];
            float a1 = As[(ty * 4 + 1) * 69 + kk];
            float a2 = As[(ty * 4 + 2) * 69 + kk];
            float a3 = As[(ty * 4 + 3) * 69 + kk];
            float b0 = Bs[(tx * 4 + 0) * 69 + kk];
            float b1 = Bs[(tx * 4 + 1) * 69 + kk];
            float b2 = Bs[(tx * 4 + 2) * 69 + kk];
            float b3 = Bs[(tx * 4 + 3) * 69 + kk];
            acc[0][0] = fmaf(a0, b0, acc[0][0]);
            acc[0][1] = fmaf(a0, b1, acc[0][1]);
            acc[0][2] = fmaf(a0, b2, acc[0][2]);
            acc[0][3] = fmaf(a0, b3, acc[0][3]);
            acc[1][0] = fmaf(a1, b0, acc[1][0]);
            acc[1][1] = fmaf(a1, b1, acc[1][1]);
            acc[1][2] = fmaf(a1, b2, acc[1][2]);
            acc[1][3] = fmaf(a1, b3, acc[1][3]);
            acc[2][0] = fmaf(a2, b0, acc[2][0]);
            acc[2][1] = fmaf(a2, b1, acc[2][1]);
            acc[2][2] = fmaf(a2, b2, acc[2][2]);
            acc[2][3] = fmaf(a2, b3, acc[2][3]);
            acc[3][0] = fmaf(a3, b0, acc[3][0]);
            acc[3][1] = fmaf(a3, b1, acc[3][1]);
            acc[3][2] = fmaf(a3, b2, acc[3][2]);
            acc[3][3] = fmaf(a3, b3, acc[3][3]);
        }
        __syncthreads();
    }

    float* gp = g_gates + (size_t)(t * 64) * G4 + nb * 64;
#pragma unroll
    for (int r = 0; r < 4; r++) {
        float4 v;
        v.x = acc[r][0] + bias_s[tx * 4 + 0];
        v.y = acc[r][1] + bias_s[tx * 4 + 1];
        v.z = acc[r][2] + bias_s[tx * 4 + 2];
        v.w = acc[r][3] + bias_s[tx * 4 + 3];
        *reinterpret_cast<float4*>(gp + (size_t)(ty * 4 + r) * G4 + tx * 4) = v;
    }
}

// ---------------- persistent LSTM scan (FFMA2 + pipelined staging) ---------------
// CTA owns j in [cta*4, cta*4+4). Thread: b = tid>>2, jl = tid&3.
// Wp: pair-packed W_hh slice  Wp[p][jl][g][{2p,2p+1}]  (32 KB, staged once).
// hs: row-major h [b][k], pitch PH=516 floats -> conflict-free STS.128 staging and
//     conflict-free ld.shared.b64 k-pair reads (bank = 4(b+k) mod 32).
// GEMV accumulates in f32x2: lo half = even-k partials, hi half = odd-k partials.
// k is split into 4 chunks of 128; chunk c+1 is staged (LDG+STS) while chunk c's
// GEMV runs, hiding the 128KB/CTA h broadcast under the FFMA2 floor.
__global__ __launch_bounds__(256, 1) void scan_kernel(const float* __restrict__ Whh,
                                                      const int* __restrict__ lengths,
                                                      float* __restrict__ d_out) {
    extern __shared__ float sm[];
    float* Wp = sm;                 // 256*4*4*2 = 8192 floats (32 KB)
    float* hs = sm + 8192;          // 64 * 516  = 33024 floats (129 KB)

    const int tid = threadIdx.x;
    const int b   = tid >> 2;      // 0..63
    const int jl  = tid & 3;       // 0..3
    const int j   = blockIdx.x * 4 + jl;

    // stage Wp: idx = p*32 + jl_*8 + g*2 + par  ->  Whh[(g*512 + j0+jl_)*512 + 2p+par]
    for (int idx = tid; idx < 8192; idx += 256) {
        int par = idx & 1;
        int g   = (idx >> 1) & 3;
        int jj  = (idx >> 3) & 3;
        int p   = idx >> 5;
        Wp[idx] = Whh[((size_t)(g * 512 + blockIdx.x * 4 + jj)) * 512 + 2 * p + par];
    }

    float c_reg = 0.f;
    const int len_b = lengths[b];

    const float4* gx4 = reinterpret_cast<const float4*>(g_gates);
    float* hT = d_out + (size_t)BB * TT * HH;
    float* cT = hT + BB * HH;

    const unsigned hs_s  = smem_u32(hs);
    const unsigned wp_s  = smem_u32(Wp);
    const unsigned hrow  = hs_s + (unsigned)(b * PH) * 4u;      // byte addr of hs[b][0]
    const unsigned wbase = wp_s + (unsigned)(jl * 8) * 4u;      // byte addr of Wp[0][jl][0][0]

    __syncthreads();

    for (int t = 0; t < TT; t++) {
        const float4* gh4 = reinterpret_cast<const float4*>(g_h[t & 1]);
        float*        ghw = g_h[(t + 1) & 1];

        // prefetch this step's gx (independent of h)
        float4 gx = __ldg(&gx4[(size_t)(t * BB + b) * 512 + j]);

        unsigned long long acc0 = pk2(gx.x, 0.f);
        unsigned long long acc1 = pk2(gx.y, 0.f);
        unsigned long long acc2 = pk2(gx.z, 0.f);
        unsigned long long acc3 = pk2(gx.w, 0.f);

        // ---- stage chunk 0 ----
#pragma unroll
        for (int i = 0; i < 8; i++) {
            int idx = i * 256 + tid;           // 0..2047
            int b2  = idx >> 5;                // 0..63
            int q   = idx & 31;                // float4 within chunk row
            float4 v = __ldcg(&gh4[b2 * 128 + q]);
            sts_v4f32(hs_s + (unsigned)(b2 * PH + q * 4) * 4u, v);
        }
        __syncthreads();

#pragma unroll
        for (int c = 0; c < 4; c++) {
            // stage chunk c+1 while computing chunk c
            if (c < 3) {
#pragma unroll
                for (int i = 0; i < 8; i++) {
                    int idx = i * 256 + tid;
                    int b2  = idx >> 5;
                    int q   = idx & 31;
                    float4 v = __ldcg(&gh4[b2 * 128 + (c + 1) * 32 + q]);
                    sts_v4f32(hs_s + (unsigned)(b2 * PH + ((c + 1) * 32 + q) * 4) * 4u, v);
                }
            }
            // GEMV over pairs p in [c*64, c*64+64)
#pragma unroll 16
            for (int p = c * 64; p < c * 64 + 64; p++) {
                unsigned long long h2 = lds_b64(hrow + (unsigned)(2 * p) * 4u);
                unsigned long long w0, w1, w2, w3;
                unsigned wa = wbase + (unsigned)(p * 32) * 4u;
                lds_v2u64(wa,       w0, w1);
                lds_v2u64(wa + 16u, w2, w3);
                FFMA2(acc0, h2, w0);
                FFMA2(acc1, h2, w1);
                FFMA2(acc2, h2, w2);
                FFMA2(acc3, h2, w3);
            }
            __syncthreads();
        }

        // ---- reduce f32x2 halves, activations, state update ----
        float2 r0 = upk2(acc0), r1 = upk2(acc1), r2 = upk2(acc2), r3 = upk2(acc3);
        float si = r0.x + r0.y;
        float sf = r1.x + r1.y;
        float sg = r2.x + r2.y;
        float so = r3.x + r3.y;

        float ig = 1.f / (1.f + __expf(-si));
        float fg = 1.f / (1.f + __expf(-sf));
        float gg = tanhf(sg);
        float og = 1.f / (1.f + __expf(-so));
        float c_new = fg * c_reg + ig * gg;
        float h_new = og * tanhf(c_new);

        float h_prev = hs[b * PH + j];
        float m  = (t < len_b) ? 1.f : 0.f;
        float h_nx = m * h_new + (1.f - m) * h_prev;
        float c_nx = m * c_new + (1.f - m) * c_reg;

        d_out[((size_t)b * TT + t) * HH + j] = h_nx;

        float rr = (float)g_rT[t * BB + b];
        c_reg = c_nx * (1.f - rr);
        float h_carry = h_nx * (1.f - rr);
        ghw[b * HH + j] = h_carry;

        if (t == TT - 1) {
            hT[b * HH + j] = h_carry;
            cT[b * HH + j] = c_reg;
        }

        // ---- grid barrier: orders this step's carry writes before next step's reads
        __threadfence();
        __syncthreads();
        if (t < TT - 1) {
            if (tid == 0) {
                unsigned arrived = atomicAdd(&g_bar[t], 1u) + 1u;
                if (arrived < (unsigned)NCTA) {
                    while (*((volatile unsigned*)&g_bar[t]) < (unsigned)NCTA) {
                        __nanosleep(64);
                    }
                }
            }
            __syncthreads();
        }
    }
}

// ---------------- launch ---------------------------------------------------------
extern "C" void kernel_launch(void* const* d_in, const int* in_sizes, int n_in,
                              void* d_out, int out_size) {
    const int*   inputs  = (const int*)d_in[0];
    const int*   lengths = (const int*)d_in[1];
    const int*   resets  = (const int*)d_in[2];
    const float* emb     = (const float*)d_in[3];
    const float* Wih     = (const float*)d_in[4];
    const float* Whh     = (const float*)d_in[5];
    const float* bih     = (const float*)d_in[6];
    const float* bhh     = (const float*)d_in[7];
    float* out = (float*)d_out;
    float* out_mask = out + (size_t)BB * TT * HH + 2 * (size_t)BB * HH;

    const int SMEM_SCAN = (8192 + 64 * PH) * (int)sizeof(float);  // 164864 B
    cudaFuncSetAttribute(scan_kernel, cudaFuncAttributeMaxDynamicSharedMemorySize, SMEM_SCAN);

    init_kernel<<<128, 256>>>(lengths, resets, out_mask);
    gates_kernel<<<dim3(32, 512), 256>>>(inputs, emb, Wih, bih, bhh);
    scan_kernel<<<NCTA, 256, SMEM_SCAN>>>(Whh, lengths, out);
}